// round 3
// baseline (speedup 1.0000x reference)
#include <cuda_runtime.h>
#include <cuda_bf16.h>
#include <cstdint>
#include <math.h>

#define B_   16
#define N_   1024
#define P_   8
#define H_   300
#define HP_  320
#define MT   128
#define NC   64
#define NCT  5
#define KC   32
#define NKT  10

// ---------------- scratch (device globals; no allocs) ----------------
__device__ __align__(16) __nv_bfloat16 g_Wh[P_ * HP_ * HP_];  // 1.6 MB
__device__ __align__(16) __nv_bfloat16 g_Wl[P_ * HP_ * HP_];  // 1.6 MB
__device__ float g_partial[NCT * B_ * N_];

// ---------------- helpers ----------------
__device__ __forceinline__ float warp_sum(float v) {
#pragma unroll
    for (int o = 16; o; o >>= 1) v += __shfl_xor_sync(0xffffffffu, v, o);
    return v;
}
__device__ __forceinline__ float warp_max(float v) {
#pragma unroll
    for (int o = 16; o; o >>= 1) v = fmaxf(v, __shfl_xor_sync(0xffffffffu, v, o));
    return v;
}

__device__ __forceinline__ void split_pair(float x, float y, uint32_t& h, uint32_t& l) {
    __nv_bfloat16 hx = __float2bfloat16_rn(x);
    __nv_bfloat16 hy = __float2bfloat16_rn(y);
    __nv_bfloat16 lx = __float2bfloat16_rn(x - __bfloat162float(hx));
    __nv_bfloat16 ly = __float2bfloat16_rn(y - __bfloat162float(hy));
    h = (uint32_t)__bfloat16_as_ushort(hx) | ((uint32_t)__bfloat16_as_ushort(hy) << 16);
    l = (uint32_t)__bfloat16_as_ushort(lx) | ((uint32_t)__bfloat16_as_ushort(ly) << 16);
}

// m16n8k16 row.col bf16 -> f32 accumulate (legacy tensor path, valid on sm_100)
__device__ __forceinline__ void mma_bf16(float* c, const uint32_t* a, const uint32_t* b) {
    asm("mma.sync.aligned.m16n8k16.row.col.f32.bf16.bf16.f32 "
        "{%0,%1,%2,%3},{%4,%5,%6,%7},{%8,%9},{%0,%1,%2,%3};"
        : "+f"(c[0]), "+f"(c[1]), "+f"(c[2]), "+f"(c[3])
        : "r"(a[0]), "r"(a[1]), "r"(a[2]), "r"(a[3]), "r"(b[0]), "r"(b[1]));
}

// ===========================================================================
// K1: split + transpose W:  g_W{h,l}[p][ko][h] = bf16split(W[p][h][ko])
// ===========================================================================
__global__ void prep_w(const float* __restrict__ W) {
    int idx = blockIdx.x * blockDim.x + threadIdx.x;
    const int total = P_ * HP_ * HP_;
    if (idx >= total) return;
    int h  = idx % HP_;
    int ko = (idx / HP_) % HP_;
    int p  = idx / (HP_ * HP_);
    float v = (h < H_ && ko < H_) ? W[((size_t)p * H_ + h) * H_ + ko] : 0.f;
    __nv_bfloat16 hi = __float2bfloat16_rn(v);
    __nv_bfloat16 lo = __float2bfloat16_rn(v - __bfloat162float(hi));
    g_Wh[idx] = hi;
    g_Wl[idx] = lo;
}

// ===========================================================================
// K2: fused bf16x3 mma.sync GEMM + P-reduce + normalize + elu + wss dot
// grid (5, 8, 16), 256 threads = 8 warps (4m x 2n), warp tile 32x32
// dynamic smem: 2 stages x [Ah 128x40 | Al | Bh 64x40 | Bl] = 61440 B
// ===========================================================================
#define STG_HALFS 15360     // 30720 B per stage in bf16 units
#define AL_OFF    5120
#define BH_OFF    10240
#define BL_OFF    12800
#define RSTRIDE   40        // row stride in halfs (32 data + 8 pad) = 80 B

__global__ __launch_bounds__(256)
void fused_gemm(const float* __restrict__ na,
                const float* __restrict__ instr,
                const float* __restrict__ sim,
                const float* __restrict__ wss) {
    extern __shared__ __nv_bfloat16 dsm[];
    __shared__ float sInstr[HP_];
    __shared__ float red[2][MT];

    const int t = threadIdx.x, lane = t & 31, wid = t >> 5;
    const int g = lane >> 2, tq = lane & 3;
    const int b = blockIdx.z, m0 = blockIdx.y * MT, n0 = blockIdx.x * NC;
    const int wm = wid & 3, wn = wid >> 2;
    const int m_w = wm * 32, n_w = wn * 32;

    for (int i = t; i < HP_; i += 256) sInstr[i] = (i < H_) ? instr[b * H_ + i] : 0.f;
    __syncthreads();

    // staging registers for next chunk
    float4 Ar[4];
    uint4  Bhr, Blr;

    // thread's fixed (row, c8) for staging
    const int ar0 = t >> 2, ac8 = t & 3;          // i=0 slice; i=1 adds 64 rows
    const int br0 = t >> 2, bc8 = t & 3;

    float sacc[2][4][4], qacc[2][4][4];
#pragma unroll
    for (int mf = 0; mf < 2; mf++)
#pragma unroll
        for (int nf = 0; nf < 4; nf++)
#pragma unroll
            for (int e = 0; e < 4; e++) { sacc[mf][nf][e] = 0.f; qacc[mf][nf][e] = 0.f; }

    float c[2][4][4];

    // ---- gmem chunk loader (p, kt) -> regs ----
    auto load_chunk = [&](int p, int kt) {
#pragma unroll
        for (int i = 0; i < 2; i++) {
            int row = ar0 + i * 64;
            int h = kt * KC + ac8 * 8;
            const float* ap = na + ((size_t)((b * N_ + m0 + row) * P_ + p)) * H_;
            float4 v0 = make_float4(0.f, 0.f, 0.f, 0.f);
            float4 v1 = make_float4(0.f, 0.f, 0.f, 0.f);
            if (h < H_) {
                v0 = *(const float4*)(ap + h);
                v0.x *= sInstr[h]; v0.y *= sInstr[h + 1];
                v0.z *= sInstr[h + 2]; v0.w *= sInstr[h + 3];
            }
            if (h + 4 < H_) {
                v1 = *(const float4*)(ap + h + 4);
                v1.x *= sInstr[h + 4]; v1.y *= sInstr[h + 5];
                v1.z *= sInstr[h + 6]; v1.w *= sInstr[h + 7];
            }
            Ar[2 * i] = v0; Ar[2 * i + 1] = v1;
        }
        {
            size_t gi = ((size_t)(p * HP_ + n0 + br0)) * HP_ + kt * KC + bc8 * 8;
            Bhr = *(const uint4*)(g_Wh + gi);
            Blr = *(const uint4*)(g_Wl + gi);
        }
    };
    // ---- regs -> smem stage (split A to bf16 hi/lo) ----
    auto store_chunk = [&](int s) {
        __nv_bfloat16* Ah = dsm + s * STG_HALFS;
        __nv_bfloat16* Al = Ah + AL_OFF;
        __nv_bfloat16* Bh = Ah + BH_OFF;
        __nv_bfloat16* Bl = Ah + BL_OFF;
#pragma unroll
        for (int i = 0; i < 2; i++) {
            int row = ar0 + i * 64;
            uint4 hv, lv;
            split_pair(Ar[2 * i].x, Ar[2 * i].y, hv.x, lv.x);
            split_pair(Ar[2 * i].z, Ar[2 * i].w, hv.y, lv.y);
            split_pair(Ar[2 * i + 1].x, Ar[2 * i + 1].y, hv.z, lv.z);
            split_pair(Ar[2 * i + 1].z, Ar[2 * i + 1].w, hv.w, lv.w);
            *(uint4*)(Ah + row * RSTRIDE + ac8 * 8) = hv;
            *(uint4*)(Al + row * RSTRIDE + ac8 * 8) = lv;
        }
        *(uint4*)(Bh + br0 * RSTRIDE + bc8 * 8) = Bhr;
        *(uint4*)(Bl + br0 * RSTRIDE + bc8 * 8) = Blr;
    };

    // prologue: chunk 0 staged
    load_chunk(0, 0);
    store_chunk(0);
    __syncthreads();

    int p = 0, kt = 0;
#pragma unroll 1
    for (int it = 0; it < P_ * NKT; ++it) {
        const int s = it & 1;

        if (kt == 0) {
#pragma unroll
            for (int mf = 0; mf < 2; mf++)
#pragma unroll
                for (int nf = 0; nf < 4; nf++)
#pragma unroll
                    for (int e = 0; e < 4; e++) c[mf][nf][e] = 0.f;
        }

        // prefetch next chunk into regs (overlaps with mma below)
        int pn = p, ktn = kt + 1;
        if (ktn == NKT) { ktn = 0; pn = p + 1; }
        const bool has_next = (it < P_ * NKT - 1);
        if (has_next) load_chunk(pn, ktn);

        // ---- mma over stage s ----
        const __nv_bfloat16* Ah = dsm + s * STG_HALFS;
        const __nv_bfloat16* Al = Ah + AL_OFF;
        const __nv_bfloat16* Bh = Ah + BH_OFF;
        const __nv_bfloat16* Bl = Ah + BL_OFF;
#pragma unroll
        for (int kkI = 0; kkI < 2; kkI++) {
            const int kk = kkI * 16;
            uint32_t ah[2][4], al[2][4], bh[4][2], bl[4][2];
#pragma unroll
            for (int mf = 0; mf < 2; mf++) {
                const int r = m_w + mf * 16 + g;
                ah[mf][0] = *(const uint32_t*)(Ah + r * RSTRIDE + kk + 2 * tq);
                ah[mf][1] = *(const uint32_t*)(Ah + (r + 8) * RSTRIDE + kk + 2 * tq);
                ah[mf][2] = *(const uint32_t*)(Ah + r * RSTRIDE + kk + 2 * tq + 8);
                ah[mf][3] = *(const uint32_t*)(Ah + (r + 8) * RSTRIDE + kk + 2 * tq + 8);
                al[mf][0] = *(const uint32_t*)(Al + r * RSTRIDE + kk + 2 * tq);
                al[mf][1] = *(const uint32_t*)(Al + (r + 8) * RSTRIDE + kk + 2 * tq);
                al[mf][2] = *(const uint32_t*)(Al + r * RSTRIDE + kk + 2 * tq + 8);
                al[mf][3] = *(const uint32_t*)(Al + (r + 8) * RSTRIDE + kk + 2 * tq + 8);
            }
#pragma unroll
            for (int nf = 0; nf < 4; nf++) {
                const int r = n_w + nf * 8 + g;
                bh[nf][0] = *(const uint32_t*)(Bh + r * RSTRIDE + kk + 2 * tq);
                bh[nf][1] = *(const uint32_t*)(Bh + r * RSTRIDE + kk + 2 * tq + 8);
                bl[nf][0] = *(const uint32_t*)(Bl + r * RSTRIDE + kk + 2 * tq);
                bl[nf][1] = *(const uint32_t*)(Bl + r * RSTRIDE + kk + 2 * tq + 8);
            }
#pragma unroll
            for (int mf = 0; mf < 2; mf++)
#pragma unroll
                for (int nf = 0; nf < 4; nf++) {
                    mma_bf16(c[mf][nf], ah[mf], bh[nf]);   // hi*hi
                    mma_bf16(c[mf][nf], ah[mf], bl[nf]);   // hi*lo
                    mma_bf16(c[mf][nf], al[mf], bh[nf]);   // lo*hi
                }
        }

        if (has_next) store_chunk(s ^ 1);
        __syncthreads();

        if (kt == NKT - 1) {
            const float sp = sim[b * P_ + p];
#pragma unroll
            for (int mf = 0; mf < 2; mf++)
#pragma unroll
                for (int nf = 0; nf < 4; nf++)
#pragma unroll
                    for (int e = 0; e < 4; e++) {
                        float sv = sp * c[mf][nf][e];
                        sacc[mf][nf][e] += sv;
                        qacc[mf][nf][e] = fmaf(sv, sv, qacc[mf][nf][e]);
                    }
        }
        p = pn; kt = ktn;
    }

    // ---- epilogue: normalize over P, elu, dot wss, reduce over columns ----
    float v4[4] = {0.f, 0.f, 0.f, 0.f};
#pragma unroll
    for (int mf = 0; mf < 2; mf++)
#pragma unroll
        for (int nf = 0; nf < 4; nf++)
#pragma unroll
            for (int e = 0; e < 4; e++) {
                int ko = n0 + n_w + nf * 8 + 2 * tq + (e & 1);
                float w = (ko < H_) ? wss[ko] : 0.f;
                float q = qacc[mf][nf][e];
                float sv = sacc[mf][nf][e];
                float nrm = fmaxf(sqrtf(q), 1e-12f);
                float sc = sv / nrm;
                float el = sc > 0.f ? sc : expm1f(sc);
                v4[mf * 2 + (e >> 1)] += el * w;
            }
#pragma unroll
    for (int j = 0; j < 4; j++) {
        v4[j] += __shfl_xor_sync(0xffffffffu, v4[j], 1);
        v4[j] += __shfl_xor_sync(0xffffffffu, v4[j], 2);
    }
    if (tq == 0) {
#pragma unroll
        for (int mf = 0; mf < 2; mf++)
#pragma unroll
            for (int hh = 0; hh < 2; hh++)
                red[wn][m_w + mf * 16 + hh * 8 + g] = v4[mf * 2 + hh];
    }
    __syncthreads();
    if (t < MT)
        g_partial[((size_t)blockIdx.x * B_ + b) * N_ + m0 + t] = red[0][t] + red[1][t];
}

// ===========================================================================
// K3: combine partials + mask, softmax over N per batch
// ===========================================================================
__global__ __launch_bounds__(1024)
void softmax_kernel(const float* __restrict__ mask, float* __restrict__ out) {
    const int b = blockIdx.x, t = threadIdx.x;
    float v = mask[b * N_ + t];
#pragma unroll
    for (int i = 0; i < NCT; i++) v += g_partial[((size_t)i * B_ + b) * N_ + t];

    __shared__ float red[32];
    const int lane = t & 31, wid = t >> 5;

    float m = warp_max(v);
    if (lane == 0) red[wid] = m;
    __syncthreads();
    if (wid == 0) red[lane] = warp_max(red[lane]);
    __syncthreads();
    m = red[0];
    __syncthreads();

    float e = expf(v - m);
    float s = warp_sum(e);
    if (lane == 0) red[wid] = s;
    __syncthreads();
    if (wid == 0) red[lane] = warp_sum(red[lane]);
    __syncthreads();
    s = red[0];

    out[b * N_ + t] = e / s;
}

// ===========================================================================
extern "C" void kernel_launch(void* const* d_in, const int* in_sizes, int n_in,
                              void* d_out, int out_size) {
    const float* node_attr = (const float*)d_in[0];
    const float* instr     = (const float*)d_in[2];
    const float* sim       = (const float*)d_in[4];
    const float* mask      = (const float*)d_in[5];
    const float* W         = (const float*)d_in[6];
    const float* wss       = (const float*)d_in[7];
    float* out = (float*)d_out;

    cudaFuncSetAttribute(fused_gemm, cudaFuncAttributeMaxDynamicSharedMemorySize, 61440);

    const int total = P_ * HP_ * HP_;
    prep_w<<<(total + 255) / 256, 256>>>(W);

    dim3 g2(NCT, N_ / MT, B_);   // (5, 8, 16)
    fused_gemm<<<g2, 256, 61440>>>(node_attr, instr, sim, wss);

    softmax_kernel<<<B_, 1024>>>(mask, out);
}

// round 4
// speedup vs baseline: 2.4155x; 2.4155x over previous
#include <cuda_runtime.h>
#include <cuda_bf16.h>
#include <cstdint>
#include <math.h>

#define B_   16
#define N_   1024
#define P_   8
#define H_   300
#define HP_  320
#define MT   128
#define NC   64
#define NCT  5      // 320/64
#define KC   32
#define NKT  10     // 320/32

// ---------------- device-global scratch ----------------
__device__ __align__(16) __nv_bfloat16 g_Wh[P_ * HP_ * HP_];            // 1.6 MB
__device__ __align__(16) __nv_bfloat16 g_Wl[P_ * HP_ * HP_];            // 1.6 MB
__device__ __align__(16) __nv_bfloat16 g_Ah[(size_t)B_ * N_ * P_ * HP_]; // 84 MB
__device__ __align__(16) __nv_bfloat16 g_Al[(size_t)B_ * N_ * P_ * HP_]; // 84 MB
__device__ float g_Y[(size_t)B_ * P_ * N_ * HP_];                        // 168 MB
__device__ float g_logits[B_ * N_];

// ---------------- helpers ----------------
__device__ __forceinline__ float warp_sum(float v) {
#pragma unroll
    for (int o = 16; o; o >>= 1) v += __shfl_xor_sync(0xffffffffu, v, o);
    return v;
}
__device__ __forceinline__ float warp_max(float v) {
#pragma unroll
    for (int o = 16; o; o >>= 1) v = fmaxf(v, __shfl_xor_sync(0xffffffffu, v, o));
    return v;
}
__device__ __forceinline__ uint32_t smem_u32(const void* p) {
    uint32_t a;
    asm("{ .reg .u64 t; cvta.to.shared.u64 t, %1; cvt.u32.u64 %0, t; }" : "=r"(a) : "l"(p));
    return a;
}
__device__ __forceinline__ void cpa16(uint32_t dst, const void* src) {
    asm volatile("cp.async.cg.shared.global [%0], [%1], 16;" :: "r"(dst), "l"(src));
}
#define CPA_COMMIT() asm volatile("cp.async.commit_group;")
#define CPA_WAIT1()  asm volatile("cp.async.wait_group 1;")

__device__ __forceinline__ void ldm4(uint32_t* r, uint32_t a) {
    asm volatile("ldmatrix.sync.aligned.m8n8.x4.shared.b16 {%0,%1,%2,%3}, [%4];"
                 : "=r"(r[0]), "=r"(r[1]), "=r"(r[2]), "=r"(r[3]) : "r"(a));
}
__device__ __forceinline__ void mma_bf16(float* c, const uint32_t* a, const uint32_t* b) {
    asm("mma.sync.aligned.m16n8k16.row.col.f32.bf16.bf16.f32 "
        "{%0,%1,%2,%3},{%4,%5,%6,%7},{%8,%9},{%0,%1,%2,%3};"
        : "+f"(c[0]), "+f"(c[1]), "+f"(c[2]), "+f"(c[3])
        : "r"(a[0]), "r"(a[1]), "r"(a[2]), "r"(a[3]), "r"(b[0]), "r"(b[1]));
}

// ===========================================================================
// K1: g_W{h,l}[p][ko][h] = bf16split(W[p][h][ko])  (transposed, zero-padded)
// ===========================================================================
__global__ void prep_w(const float* __restrict__ W) {
    int idx = blockIdx.x * blockDim.x + threadIdx.x;
    const int total = P_ * HP_ * HP_;
    if (idx >= total) return;
    int h  = idx % HP_;
    int ko = (idx / HP_) % HP_;
    int p  = idx / (HP_ * HP_);
    float v = (h < H_ && ko < H_) ? W[((size_t)p * H_ + h) * H_ + ko] : 0.f;
    __nv_bfloat16 hi = __float2bfloat16_rn(v);
    __nv_bfloat16 lo = __float2bfloat16_rn(v - __bfloat162float(hi));
    g_Wh[idx] = hi;
    g_Wl[idx] = lo;
}

// ===========================================================================
// K2: g_A{h,l}[b][n][p][hp] = bf16split(instr[b][h] * na[b][n][p][h])
// one float4-worth per thread
// ===========================================================================
__global__ void prep_a(const float* __restrict__ na, const float* __restrict__ instr) {
    int idx = blockIdx.x * blockDim.x + threadIdx.x;
    const int total = B_ * N_ * P_ * (HP_ / 4);
    if (idx >= total) return;
    int hq   = idx % (HP_ / 4);
    int rest = idx / (HP_ / 4);              // (b*N + n)*P + p
    int h    = hq * 4;
    int b    = rest >> 13;                   // / (N_*P_) = /8192
    float4 v = make_float4(0.f, 0.f, 0.f, 0.f);
    if (h < H_) {
        v = *(const float4*)(na + (size_t)rest * H_ + h);
        const float* ib = instr + b * H_ + h;
        v.x *= ib[0]; v.y *= ib[1]; v.z *= ib[2]; v.w *= ib[3];
    }
    __nv_bfloat16 h0 = __float2bfloat16_rn(v.x), h1 = __float2bfloat16_rn(v.y);
    __nv_bfloat16 h2 = __float2bfloat16_rn(v.z), h3 = __float2bfloat16_rn(v.w);
    __nv_bfloat16 l0 = __float2bfloat16_rn(v.x - __bfloat162float(h0));
    __nv_bfloat16 l1 = __float2bfloat16_rn(v.y - __bfloat162float(h1));
    __nv_bfloat16 l2 = __float2bfloat16_rn(v.z - __bfloat162float(h2));
    __nv_bfloat16 l3 = __float2bfloat16_rn(v.w - __bfloat162float(h3));
    uint2 hv = make_uint2(
        (uint32_t)__bfloat16_as_ushort(h0) | ((uint32_t)__bfloat16_as_ushort(h1) << 16),
        (uint32_t)__bfloat16_as_ushort(h2) | ((uint32_t)__bfloat16_as_ushort(h3) << 16));
    uint2 lv = make_uint2(
        (uint32_t)__bfloat16_as_ushort(l0) | ((uint32_t)__bfloat16_as_ushort(l1) << 16),
        (uint32_t)__bfloat16_as_ushort(l2) | ((uint32_t)__bfloat16_as_ushort(l3) << 16));
    *(uint2*)(g_Ah + (size_t)idx * 4) = hv;
    *(uint2*)(g_Al + (size_t)idx * 4) = lv;
}

// ===========================================================================
// K3: batched GEMM, bf16x3 via mma.sync + ldmatrix + cp.async double buffer
// grid (NCT, N/MT, B*P) = (5, 8, 128); 256 thr = 8 warps (4m x 2n), warp 32x32
// smem: 2 stages x [Ah 128x40h | Al | Bh 64x40h | Bl] halfs, stride 80 B
// ===========================================================================
#define RSTR_B    80                     // row stride bytes
#define A_BYTES   (128 * RSTR_B)         // 10240
#define Bt_BYTES  (64 * RSTR_B)          // 5120
#define STG_BYTES (2 * A_BYTES + 2 * Bt_BYTES)  // 30720
#define OAL  A_BYTES
#define OBH  (2 * A_BYTES)
#define OBL  (2 * A_BYTES + Bt_BYTES)

__global__ __launch_bounds__(256)
void gemm(int dummy) {
    extern __shared__ char sm[];
    const uint32_t sbase = smem_u32(sm);

    const int t = threadIdx.x, lane = t & 31, wid = t >> 5;
    const int g = lane >> 2, tq = lane & 3;
    const int bp = blockIdx.z, b = bp >> 3, p = bp & 7;
    const int m0 = blockIdx.y * MT, n0 = blockIdx.x * NC;
    const int wm = wid & 3, wn = wid >> 2;
    const int m_w = wm * 32, n_w = wn * 32;

    // cp.async indexing
    const int arow = t >> 2, aseg = t & 3;       // +64 rows for the second half
    // ldmatrix lane offsets
    const uint32_t aoff = (uint32_t)((lane & 15) * RSTR_B + ((lane >> 4) << 4));
    const uint32_t boff = (uint32_t)((((lane & 7) + ((lane >> 4) << 3)) * RSTR_B) +
                                     (((lane >> 3) & 1) << 4));

    const size_t a_gbase = ((size_t)(b * N_ + m0) * P_ + p) * HP_;
    const size_t b_gbase = ((size_t)p * HP_ + n0) * HP_;

    auto issue = [&](int kt, int s) {
        const uint32_t st = sbase + s * STG_BYTES;
        const int kh = kt * KC + aseg * 8;
#pragma unroll
        for (int i = 0; i < 2; i++) {
            int row = arow + i * 64;
            size_t gi = a_gbase + (size_t)row * (P_ * HP_) + kh;
            uint32_t so = (uint32_t)(row * RSTR_B + aseg * 16);
            cpa16(st + so, g_Ah + gi);
            cpa16(st + OAL + so, g_Al + gi);
        }
        {
            size_t gi = b_gbase + (size_t)arow * HP_ + kh;   // arow<64 rows for B
            uint32_t so = (uint32_t)(arow * RSTR_B + aseg * 16);
            if (arow < 64) {
                cpa16(st + OBH + so, g_Wh + gi);
                cpa16(st + OBL + so, g_Wl + gi);
            }
        }
    };

    float c[2][4][4];
#pragma unroll
    for (int mf = 0; mf < 2; mf++)
#pragma unroll
        for (int nf = 0; nf < 4; nf++)
#pragma unroll
            for (int e = 0; e < 4; e++) c[mf][nf][e] = 0.f;

    issue(0, 0); CPA_COMMIT();
    issue(1, 1); CPA_COMMIT();

#pragma unroll 1
    for (int kt = 0; kt < NKT; ++kt) {
        const int s = kt & 1;
        CPA_WAIT1();
        __syncthreads();
        const uint32_t st = sbase + s * STG_BYTES;

#pragma unroll
        for (int kkI = 0; kkI < 2; kkI++) {
            const uint32_t kkb = kkI * 32;   // 16 halfs = 32 bytes
            uint32_t ah[2][4], al[2][4], bh[2][4], bl[2][4];
#pragma unroll
            for (int mf = 0; mf < 2; mf++) {
                uint32_t base = st + (uint32_t)((m_w + mf * 16) * RSTR_B) + kkb + aoff;
                ldm4(ah[mf], base);
                ldm4(al[mf], base + OAL);
            }
#pragma unroll
            for (int nfp = 0; nfp < 2; nfp++) {
                uint32_t base = st + OBH + (uint32_t)((n_w + nfp * 16) * RSTR_B) + kkb + boff;
                ldm4(bh[nfp], base);
                ldm4(bl[nfp], base + Bt_BYTES);
            }
#pragma unroll
            for (int mf = 0; mf < 2; mf++)
#pragma unroll
                for (int nf = 0; nf < 4; nf++) {
                    const uint32_t* bhp = &bh[nf >> 1][(nf & 1) * 2];
                    const uint32_t* blp = &bl[nf >> 1][(nf & 1) * 2];
                    mma_bf16(c[mf][nf], ah[mf], bhp);   // hi*hi
                    mma_bf16(c[mf][nf], ah[mf], blp);   // hi*lo
                    mma_bf16(c[mf][nf], al[mf], bhp);   // lo*hi
                }
        }
        __syncthreads();
        if (kt + 2 < NKT) issue(kt + 2, s);
        CPA_COMMIT();
    }

    // store C tile to g_Y[b][p][:,:]
    float* yb = g_Y + (size_t)(b * P_ + p) * N_ * HP_;
#pragma unroll
    for (int mf = 0; mf < 2; mf++)
#pragma unroll
        for (int nf = 0; nf < 4; nf++) {
            int gr = m0 + m_w + mf * 16 + g;
            int gc = n0 + n_w + nf * 8 + 2 * tq;
            *(float2*)(yb + (size_t)gr * HP_ + gc) = make_float2(c[mf][nf][0], c[mf][nf][1]);
            *(float2*)(yb + (size_t)(gr + 8) * HP_ + gc) = make_float2(c[mf][nf][2], c[mf][nf][3]);
        }
}

// ===========================================================================
// K4: per-(b,n): sv = sim_p*y; normalize over P; elu; dot wss; + mask
// ===========================================================================
__global__ __launch_bounds__(256)
void epilogue(const float* __restrict__ sim,
              const float* __restrict__ wss,
              const float* __restrict__ mask) {
    const int bn = blockIdx.x;
    const int b  = bn >> 10;
    const int n  = bn & 1023;
    const float* base = g_Y + ((size_t)b * P_ * N_ + n) * HP_;

    float sp[P_];
#pragma unroll
    for (int p = 0; p < P_; p++) sp[p] = sim[b * P_ + p];

    float acc = 0.f;
    for (int k = threadIdx.x; k < H_; k += 256) {
        float s = 0.f, q = 0.f;
#pragma unroll
        for (int p = 0; p < P_; p++) {
            float v = sp[p] * base[(size_t)p * (N_ * HP_) + k];
            s += v;
            q = fmaf(v, v, q);
        }
        float nrm = fmaxf(sqrtf(q), 1e-12f);
        float sc  = s / nrm;
        float e   = sc > 0.f ? sc : expm1f(sc);
        acc += e * wss[k];
    }
    acc = warp_sum(acc);
    __shared__ float ws[8];
    int lane = threadIdx.x & 31, wid = threadIdx.x >> 5;
    if (lane == 0) ws[wid] = acc;
    __syncthreads();
    if (threadIdx.x == 0) {
        float s = 0.f;
#pragma unroll
        for (int i = 0; i < 8; i++) s += ws[i];
        g_logits[bn] = s + mask[bn];
    }
}

// ===========================================================================
// K5: softmax over N per batch
// ===========================================================================
__global__ __launch_bounds__(1024)
void softmax_kernel(float* __restrict__ out) {
    const int b = blockIdx.x, t = threadIdx.x;
    float v = g_logits[b * N_ + t];
    __shared__ float red[32];
    const int lane = t & 31, wid = t >> 5;

    float m = warp_max(v);
    if (lane == 0) red[wid] = m;
    __syncthreads();
    if (wid == 0) red[lane] = warp_max(red[lane]);
    __syncthreads();
    m = red[0];
    __syncthreads();

    float e = expf(v - m);
    float s = warp_sum(e);
    if (lane == 0) red[wid] = s;
    __syncthreads();
    if (wid == 0) red[lane] = warp_sum(red[lane]);
    __syncthreads();
    s = red[0];

    out[b * N_ + t] = e / s;
}

// ===========================================================================
extern "C" void kernel_launch(void* const* d_in, const int* in_sizes, int n_in,
                              void* d_out, int out_size) {
    const float* node_attr = (const float*)d_in[0];
    const float* instr     = (const float*)d_in[2];
    const float* sim       = (const float*)d_in[4];
    const float* mask      = (const float*)d_in[5];
    const float* W         = (const float*)d_in[6];
    const float* wss       = (const float*)d_in[7];
    float* out = (float*)d_out;

    cudaFuncSetAttribute(gemm, cudaFuncAttributeMaxDynamicSharedMemorySize, 2 * STG_BYTES);

    const int totW = P_ * HP_ * HP_;
    prep_w<<<(totW + 255) / 256, 256>>>(W);

    const int totA = B_ * N_ * P_ * (HP_ / 4);
    prep_a<<<(totA + 255) / 256, 256>>>(node_attr, instr);

    dim3 gg(NCT, N_ / MT, B_ * P_);   // (5, 8, 128)
    gemm<<<gg, 256, 2 * STG_BYTES>>>(0);

    epilogue<<<B_ * N_, 256>>>(sim, wss, mask);

    softmax_kernel<<<B_, 1024>>>(out);
}